// round 9
// baseline (speedup 1.0000x reference)
#include <cuda_runtime.h>
#include <math.h>

// Problem constants
#define NB    64
#define NH    512
#define NW    512
#define NPTS  200

#define EPS_LO 0.4999f
#define EPS_HI 0.5001f
#define ROWCAP 8          // borderline values stored per row (true count kept separately)
#define BPB    64         // kA blocks per batch

// bare MUFU.EX2 (no library fix-up code)
__device__ __forceinline__ float ex2_approx(float x) {
    float y;
    asm("ex2.approx.f32 %0, %1;" : "=f"(y) : "f"(x));
    return y;
}

// ---------------- scratch (device globals; every slot written every call,
// so no init kernel and no resets are needed) ----------------
__device__ float  g_pmn[NB][BPB];
__device__ float  g_pmx[NB][BPB];
// g_cnt[half][batch][row]: half 0 = cols [0,256), half 1 = cols [256,512)
__device__ float  g_cnt[2][NB][NH];
__device__ int    g_blcnt[NB][NH];          // true borderline count per row
__device__ float  g_blv[NB][NH][ROWCAP];    // packed: +v -> half 0, -v -> half 1

// ---------------- KA: fused single pass (DRAM-bound, atomic-free) --------
// One warp per row, 8 warps/block, 64 blocks/batch, grid 4096.
__global__ void kA_pass(const float4* __restrict__ in) {
    int gwarp = (blockIdx.x * blockDim.x + threadIdx.x) >> 5;  // 0..32767
    int lane  = threadIdx.x & 31;
    int b   = gwarp >> 9;
    int row = gwarp & 511;

    const float4* p = in + ((size_t)(b * NH + row)) * 256;  // 256 float4/row

    // front-batched loads: 8 independent LDG.128 in flight
    float a[16];
#pragma unroll
    for (int i = 0; i < 8; i++) {
        float4 t = p[lane + i * 32];
        a[2 * i]     = t.y;            // channel-1 of pixel 2k
        a[2 * i + 1] = t.w;            // channel-1 of pixel 2k+1
    }

    float mn = 1e30f, mx = -1e30f;
    unsigned cL = 0, cR = 0;
#pragma unroll
    for (int i = 0; i < 16; i++) {
        float v = a[i];
        mn = fminf(mn, v);
        mx = fmaxf(mx, v);
        unsigned pred = (unsigned)(v > EPS_LO);
        if (i < 8) cL += pred; else cR += pred;   // idx <8 -> cols [0,256)
    }

    // warp-enumerated borderline capture into this row's fixed slots
    int base = 0;
#pragma unroll
    for (int i = 0; i < 16; i++) {
        float v = a[i];
        bool bl = (v > EPS_LO) && (v <= EPS_HI);
        unsigned mask = __ballot_sync(0xffffffffu, bl);
        if (bl) {
            int idx = base + __popc(mask & ((1u << lane) - 1u));
            if (idx < ROWCAP)
                g_blv[b][row][idx] = (i < 8) ? v : -v;   // sign encodes half
        }
        base += __popc(mask);
    }

    cL = __reduce_add_sync(0xffffffffu, cL);
    cR = __reduce_add_sync(0xffffffffu, cR);
    if (lane == 0) {
        g_cnt[0][b][row] = (float)cL;
        g_cnt[1][b][row] = (float)cR;
        g_blcnt[b][row]  = base;       // true count (may exceed ROWCAP -> fallback)
    }

    // block-level min/max partials (no atomics)
#pragma unroll
    for (int o = 16; o; o >>= 1) {
        mn = fminf(mn, __shfl_xor_sync(0xffffffffu, mn, o));
        mx = fmaxf(mx, __shfl_xor_sync(0xffffffffu, mx, o));
    }
    __shared__ float smn[8], smx[8];
    int w = threadIdx.x >> 5;
    if (lane == 0) { smn[w] = mn; smx[w] = mx; }
    __syncthreads();
    if (threadIdx.x == 0) {
#pragma unroll
        for (int i = 1; i < 8; i++) { mn = fminf(mn, smn[i]); mx = fmaxf(mx, smx[i]); }
        g_pmn[b][blockIdx.x & 63] = mn;
        g_pmx[b][blockIdx.x & 63] = mx;
    }
}

// ---------------- K3: minmax reduce + correction + resampling ----------
// grid 256: two blocks per (batch, contour) unit, each does 128 point-slots.
// Hot loop: 4 FMA-pipe ops/row (S folded into the angle), bare MUFU.EX2,
// warp-uniform float4 SMEM broadcasts, no wrap / no clamp (provably ~0).
__global__ void __launch_bounds__(1024, 2)
k3_contour(const float4* __restrict__ in, float* __restrict__ out) {
    const float TWO_PI = 6.283185307179586f;
    const float TT0    = (float)(M_PI / 2.0);
    const float DT     = (float)(M_PI / 200.0);
    const float SQK    = 12.011224469026914f;  // sqrt(100 * log2(e))

    int b  = blockIdx.x >> 2;
    int c  = (blockIdx.x >> 1) & 1;
    int hp = blockIdx.x & 1;           // which half of the point range
    int tid = threadIdx.x;

    __shared__ float  s_x1[NH];
    __shared__ float2 s_rt[NH];        // (tt, r); read as float4 in hot loop
    __shared__ float  s_red[16];
    __shared__ float  s_bounds[2];
    __shared__ float  s_mm[2];         // mn, mx
    __shared__ int    s_ovf;
    __shared__ float  s_num[8][128];
    __shared__ float  s_den[8][128];

    // reduce the 64 min/max partials (2 warps)
    if (tid == 0) s_ovf = 0;
    if (tid < BPB) {
        float v = g_pmn[b][tid];
#pragma unroll
        for (int o = 16; o; o >>= 1) v = fminf(v, __shfl_xor_sync(0xffffffffu, v, o));
        if ((tid & 31) == 0) s_red[tid >> 5] = v;
    } else if (tid < 2 * BPB) {
        float v = g_pmx[b][tid - BPB];
#pragma unroll
        for (int o = 16; o; o >>= 1) v = fmaxf(v, __shfl_xor_sync(0xffffffffu, v, o));
        if ((tid & 31) == 0) s_red[8 + ((tid - BPB) >> 5)] = v;
    }
    int blcnt = 0;
    if (tid < NH) {
        s_x1[tid] = g_cnt[c][b][tid];
        blcnt = g_blcnt[b][tid];
        if (blcnt > ROWCAP) s_ovf = 1;   // benign race: any writer sets 1
    }
    __syncthreads();
    if (tid == 0) {
        s_mm[0] = fminf(s_red[0], s_red[1]);
        s_mm[1] = fmaxf(s_red[8], s_red[9]);
    }
    __syncthreads();
    float mn = s_mm[0], mx = s_mm[1];
    float h  = 0.5f * (mx - mn);        // exact predicate: (v - mn) > h

    // Window validity: all v <= EPS_LO must fail, all v > EPS_HI must pass.
    bool ok = ((EPS_LO - mn) <= h) && ((EPS_HI - mn) > h) && (s_ovf == 0);
    if (ok) {
        // exact correction; each thread owns its row -> no atomics
        if (tid < NH) {
            float corr = 0.f;
            for (int j = 0; j < blcnt; j++) {
                float pv = g_blv[b][tid][j];
                int   half = pv < 0.0f;
                float v = fabsf(pv);
                if (half == c && !((v - mn) > h)) corr += 1.0f;
            }
            s_x1[tid] -= corr;
        }
    } else {
        // never-expected exact fallback: full recount of this (b, c) half
        int w = tid >> 5, lane = tid & 31;
        for (int row = w; row < NH; row += 32) {
            const float4* p = in + ((size_t)(b * NH + row)) * 256 + c * 128;
            unsigned cnt = 0;
#pragma unroll
            for (int k = 0; k < 4; k++) {
                float4 v = p[lane + k * 32];
                cnt += (unsigned)((v.y - mn) > h) + (unsigned)((v.w - mn) > h);
            }
            cnt = __reduce_add_sync(0xffffffffu, cnt);
            if (lane == 0) s_x1[row] = (float)cnt;
        }
    }
    __syncthreads();

    // bounds: ythtop = 256 - sum(xa[0:256]), ythbottom = 256 + sum(xa[256:512])
    if (tid < NH) {
        float s = fminf(s_x1[tid], 1.0f);
#pragma unroll
        for (int o = 16; o; o >>= 1) s += __shfl_xor_sync(0xffffffffu, s, o);
        if ((tid & 31) == 0) s_red[tid >> 5] = s;
    }
    __syncthreads();
    if (tid == 0) {
        float st = 0.f, sb = 0.f;
#pragma unroll
        for (int i = 0; i < 8; i++)  st += s_red[i];
#pragma unroll
        for (int i = 8; i < 16; i++) sb += s_red[i];
        s_bounds[0] = 256.0f - st;
        s_bounds[1] = 256.0f + sb;
    }
    __syncthreads();

    if (tid < NH) {
        float x1 = s_x1[tid];
        float y1 = fminf(fmaxf((float)tid, s_bounds[0]), s_bounds[1]);
        float yc = y1 - 256.0f;
        float xc = -x1;
        float r  = sqrtf(xc * xc + yc * yc);
        float tt = atan2f(yc, xc);
        if (tt < 0.0f) tt += TWO_PI;   // fix_radians -> [0, 2pi)
        s_rt[tid] = make_float2(tt, r);
    }
    __syncthreads();

    // 8 partial sums per point-slot; sub = tid>>7 is warp-uniform so the
    // SMEM reads are broadcasts. Each thread handles 64 rows (32 float4).
    // Range proof: xc <= 0 -> tt in [pi/2, 3pi/2]; ttn in [pi/2, 3pi/2) ->
    //   d in (-pi, pi]: no wrap needed; +-2pi period candidates give ~0.
    // Clamp dropped: reference clamps d^2>1 to exp(-100) = 3.7e-44 ~ 0.
    // Weight: exp(-100 d^2) = ex2(-(S*d)^2), S = sqrt(100*log2(e)):
    //   t = tt*S - ttn*S (FFMA), arg = -t*t (FMUL w/ neg mod) -> 4 FMA-pipe
    //   ops per row total.
    int np  = tid & 127;             // point-slot within this half
    int sub = tid >> 7;              // 0..7, warp-uniform
    int n   = hp * 128 + np;         // global point-slot (real < 200)
    float ttnS = (TT0 + (float)n * DT) * SQK;
    float num = 0.f, den = 0.f;
    const float4* rt4 = (const float4*)s_rt;   // (tt0, r0, tt1, r1)
    int base4 = sub << 5;                      // 32 float4 per sub-range
#pragma unroll 8
    for (int m = 0; m < 32; m++) {
        float4 q = rt4[base4 + m];
        float t0 = fmaf(q.x, SQK, -ttnS);
        float w0 = ex2_approx(-t0 * t0);
        den += w0;
        num = fmaf(w0, q.y, num);
        float t1 = fmaf(q.z, SQK, -ttnS);
        float w1 = ex2_approx(-t1 * t1);
        den += w1;
        num = fmaf(w1, q.w, num);
    }
    s_num[sub][np] = num;
    s_den[sub][np] = den;
    __syncthreads();

    if (tid < 128) {
        int nn = hp * 128 + tid;
        if (nn < NPTS) {
            float nm = 0.f, dn = 0.f;
#pragma unroll
            for (int i = 0; i < 8; i++) { nm += s_num[i][tid]; dn += s_den[i][tid]; }
            float ttn0 = TT0 + (float)nn * DT;
            float rn = nm / dn;
            float x = fmaf(rn, cosf(ttn0), 256.0f);
            float y = fmaf(rn, sinf(ttn0), 256.0f);
            int idx; float xo;
            if (c == 0) { idx = nn;       xo = x; }
            else        { idx = 399 - nn; xo = 512.0f - x; }
            out[((size_t)b * 400 + idx) * 2 + 0] = xo;
            out[((size_t)b * 400 + idx) * 2 + 1] = y;
        }
    }
}

extern "C" void kernel_launch(void* const* d_in, const int* in_sizes, int n_in,
                              void* d_out, int out_size) {
    const float4* in = (const float4*)d_in[0];
    float* out = (float*)d_out;

    kA_pass<<<4096, 256>>>(in);
    k3_contour<<<256, 1024>>>(in, out);
}

// round 10
// speedup vs baseline: 1.0027x; 1.0027x over previous
#include <cuda_runtime.h>
#include <math.h>

// Problem constants
#define NB    64
#define NH    512
#define NW    512
#define NPTS  200

#define EPS_LO 0.4999f
#define EPS_HI 0.5001f
#define ROWCAP 8          // borderline values stored per row (true count kept separately)
#define BPB    64         // kA blocks per batch

// bare MUFU.EX2 (no library fix-up code)
__device__ __forceinline__ float ex2_approx(float x) {
    float y;
    asm("ex2.approx.f32 %0, %1;" : "=f"(y) : "f"(x));
    return y;
}

// ---------------- scratch (device globals; every slot written every call,
// so no init kernel and no resets are needed) ----------------
__device__ float  g_pmn[NB][BPB];
__device__ float  g_pmx[NB][BPB];
// g_cnt[half][batch][row]: half 0 = cols [0,256), half 1 = cols [256,512)
__device__ float  g_cnt[2][NB][NH];
__device__ int    g_blcnt[NB][NH];          // true borderline count per row
__device__ float  g_blv[NB][NH][ROWCAP];    // packed: +v -> half 0, -v -> half 1
__device__ float2 g_rt[2 * NB][NH];         // (tt, r) per unit (b*2+c)

// ---------------- KA: fused single pass (DRAM-bound, atomic-free) --------
// One warp per row, 8 warps/block, 64 blocks/batch, grid 4096.
__global__ void kA_pass(const float4* __restrict__ in) {
    int gwarp = (blockIdx.x * blockDim.x + threadIdx.x) >> 5;  // 0..32767
    int lane  = threadIdx.x & 31;
    int b   = gwarp >> 9;
    int row = gwarp & 511;

    const float4* p = in + ((size_t)(b * NH + row)) * 256;  // 256 float4/row

    // front-batched loads: 8 independent LDG.128 in flight
    float a[16];
#pragma unroll
    for (int i = 0; i < 8; i++) {
        float4 t = p[lane + i * 32];
        a[2 * i]     = t.y;            // channel-1 of pixel 2k
        a[2 * i + 1] = t.w;            // channel-1 of pixel 2k+1
    }

    float mn = 1e30f, mx = -1e30f;
    unsigned cL = 0, cR = 0;
#pragma unroll
    for (int i = 0; i < 16; i++) {
        float v = a[i];
        mn = fminf(mn, v);
        mx = fmaxf(mx, v);
        unsigned pred = (unsigned)(v > EPS_LO);
        if (i < 8) cL += pred; else cR += pred;   // idx <8 -> cols [0,256)
    }

    // warp-enumerated borderline capture into this row's fixed slots
    int base = 0;
#pragma unroll
    for (int i = 0; i < 16; i++) {
        float v = a[i];
        bool bl = (v > EPS_LO) && (v <= EPS_HI);
        unsigned mask = __ballot_sync(0xffffffffu, bl);
        if (bl) {
            int idx = base + __popc(mask & ((1u << lane) - 1u));
            if (idx < ROWCAP)
                g_blv[b][row][idx] = (i < 8) ? v : -v;   // sign encodes half
        }
        base += __popc(mask);
    }

    cL = __reduce_add_sync(0xffffffffu, cL);
    cR = __reduce_add_sync(0xffffffffu, cR);
    if (lane == 0) {
        g_cnt[0][b][row] = (float)cL;
        g_cnt[1][b][row] = (float)cR;
        g_blcnt[b][row]  = base;       // true count (may exceed ROWCAP -> fallback)
    }

    // block-level min/max partials (no atomics)
#pragma unroll
    for (int o = 16; o; o >>= 1) {
        mn = fminf(mn, __shfl_xor_sync(0xffffffffu, mn, o));
        mx = fmaxf(mx, __shfl_xor_sync(0xffffffffu, mx, o));
    }
    __shared__ float smn[8], smx[8];
    int w = threadIdx.x >> 5;
    if (lane == 0) { smn[w] = mn; smx[w] = mx; }
    __syncthreads();
    if (threadIdx.x == 0) {
#pragma unroll
        for (int i = 1; i < 8; i++) { mn = fminf(mn, smn[i]); mx = fmaxf(mx, smx[i]); }
        g_pmn[b][blockIdx.x & 63] = mn;
        g_pmx[b][blockIdx.x & 63] = mx;
    }
}

// ---------------- K3a: prelude per (batch, contour) unit ----------------
// grid 128, block 512. minmax reduce + exact correction + bounds + polar
// transform; writes (tt, r) to g_rt[unit].
__global__ void k3a_prelude(const float4* __restrict__ in) {
#if __CUDA_ARCH__ >= 900
    cudaGridDependencySynchronize();   // PDL: wait for kA's writes
#endif
    const float TWO_PI = 6.283185307179586f;

    int unit = blockIdx.x;
    int b = unit >> 1, c = unit & 1;
    int tid = threadIdx.x;             // == row

    __shared__ float s_x1[NH];
    __shared__ float s_red[16];
    __shared__ float s_bounds[2];
    __shared__ float s_mm[2];
    __shared__ int   s_ovf;

    if (tid == 0) s_ovf = 0;
    if (tid < BPB) {
        float v = g_pmn[b][tid];
#pragma unroll
        for (int o = 16; o; o >>= 1) v = fminf(v, __shfl_xor_sync(0xffffffffu, v, o));
        if ((tid & 31) == 0) s_red[tid >> 5] = v;
    } else if (tid < 2 * BPB) {
        float v = g_pmx[b][tid - BPB];
#pragma unroll
        for (int o = 16; o; o >>= 1) v = fmaxf(v, __shfl_xor_sync(0xffffffffu, v, o));
        if ((tid & 31) == 0) s_red[8 + ((tid - BPB) >> 5)] = v;
    }
    s_x1[tid] = g_cnt[c][b][tid];
    int blcnt = g_blcnt[b][tid];
    if (blcnt > ROWCAP) s_ovf = 1;     // benign race: any writer sets 1
    __syncthreads();
    if (tid == 0) {
        s_mm[0] = fminf(s_red[0], s_red[1]);
        s_mm[1] = fmaxf(s_red[8], s_red[9]);
    }
    __syncthreads();
    float mn = s_mm[0], mx = s_mm[1];
    float h  = 0.5f * (mx - mn);       // exact predicate: (v - mn) > h

    // Window validity: all v <= EPS_LO must fail, all v > EPS_HI must pass.
    bool ok = ((EPS_LO - mn) <= h) && ((EPS_HI - mn) > h) && (s_ovf == 0);
    if (ok) {
        float corr = 0.f;
        for (int j = 0; j < blcnt; j++) {
            float pv = g_blv[b][tid][j];
            int   half = pv < 0.0f;
            float v = fabsf(pv);
            if (half == c && !((v - mn) > h)) corr += 1.0f;
        }
        s_x1[tid] -= corr;
    } else {
        // never-expected exact fallback: full recount of this (b, c) half
        __syncthreads();
        int w = tid >> 5, lane = tid & 31;
        for (int row = w; row < NH; row += 16) {
            const float4* p = in + ((size_t)(b * NH + row)) * 256 + c * 128;
            unsigned cnt = 0;
#pragma unroll
            for (int k = 0; k < 4; k++) {
                float4 v = p[lane + k * 32];
                cnt += (unsigned)((v.y - mn) > h) + (unsigned)((v.w - mn) > h);
            }
            cnt = __reduce_add_sync(0xffffffffu, cnt);
            if (lane == 0) s_x1[row] = (float)cnt;
        }
    }
    __syncthreads();

    // bounds: ythtop = 256 - sum(xa[0:256]), ythbottom = 256 + sum(xa[256:512])
    {
        float s = fminf(s_x1[tid], 1.0f);
#pragma unroll
        for (int o = 16; o; o >>= 1) s += __shfl_xor_sync(0xffffffffu, s, o);
        if ((tid & 31) == 0) s_red[tid >> 5] = s;
    }
    __syncthreads();
    if (tid == 0) {
        float st = 0.f, sb = 0.f;
#pragma unroll
        for (int i = 0; i < 8; i++)  st += s_red[i];
#pragma unroll
        for (int i = 8; i < 16; i++) sb += s_red[i];
        s_bounds[0] = 256.0f - st;
        s_bounds[1] = 256.0f + sb;
    }
    __syncthreads();

    float x1 = s_x1[tid];
    float y1 = fminf(fmaxf((float)tid, s_bounds[0]), s_bounds[1]);
    float yc = y1 - 256.0f;
    float xc = -x1;
    float r  = sqrtf(xc * xc + yc * yc);
    float tt = atan2f(yc, xc);
    if (tt < 0.0f) tt += TWO_PI;       // fix_radians -> [0, 2pi)
    g_rt[unit][tid] = make_float2(tt, r);
}

// ---------------- K3b: Gaussian resampling ----------------
// grid 512 (= unit*4 + quarter), block 256. Each block: 64 point-slots,
// 4 partial sums each (sub = tid>>6, warp-uniform -> SMEM broadcasts).
// Range proof: xc <= 0 -> tt in [pi/2, 3pi/2]; ttn in [pi/2, 3pi/2) ->
//   d in (-pi, pi]: no wrap needed; +-2pi period candidates give ~0.
// Clamp dropped: reference clamps d^2>1 to exp(-100) ~ 3.7e-44 ~ 0.
// Weight: exp(-100 d^2) = ex2(-(S*tt - S*ttn)^2), S = sqrt(100*log2(e)).
__global__ void __launch_bounds__(256)
k3b_gauss(float* __restrict__ out) {
#if __CUDA_ARCH__ >= 900
    cudaGridDependencySynchronize();   // PDL: wait for k3a's g_rt writes
#endif
    const float TT0 = (float)(M_PI / 2.0);
    const float DT  = (float)(M_PI / 200.0);
    const float SQK = 12.011224469026914f;  // sqrt(100 * log2(e))

    int unit = blockIdx.x >> 2;
    int q    = blockIdx.x & 3;
    int b = unit >> 1, c = unit & 1;
    int tid = threadIdx.x;

    __shared__ float4 s_rt4[NH / 2];   // 512 x (tt,r) as 256 float4
    __shared__ float  s_num[4][64];
    __shared__ float  s_den[4][64];

    s_rt4[tid] = ((const float4*)g_rt[unit])[tid];
    __syncthreads();

    int np  = tid & 63;                // point-slot within this quarter
    int sub = tid >> 6;                // 0..3, warp-uniform
    int n   = q * 64 + np;             // global point-slot (real < 200)
    float ttnS = (TT0 + (float)n * DT) * SQK;
    float num = 0.f, den = 0.f;
    int base4 = sub << 6;              // 64 float4 per sub-range (128 rows)
#pragma unroll 8
    for (int m = 0; m < 64; m++) {
        float4 v = s_rt4[base4 + m];
        float t0 = fmaf(v.x, SQK, -ttnS);
        float w0 = ex2_approx(-t0 * t0);
        den += w0;
        num = fmaf(w0, v.y, num);
        float t1 = fmaf(v.z, SQK, -ttnS);
        float w1 = ex2_approx(-t1 * t1);
        den += w1;
        num = fmaf(w1, v.w, num);
    }
    s_num[sub][np] = num;
    s_den[sub][np] = den;
    __syncthreads();

    if (tid < 64) {
        int nn = q * 64 + tid;
        if (nn < NPTS) {
            float nm = s_num[0][tid] + s_num[1][tid] + s_num[2][tid] + s_num[3][tid];
            float dn = s_den[0][tid] + s_den[1][tid] + s_den[2][tid] + s_den[3][tid];
            float ttn0 = TT0 + (float)nn * DT;
            float rn = nm / dn;
            float x = fmaf(rn, cosf(ttn0), 256.0f);
            float y = fmaf(rn, sinf(ttn0), 256.0f);
            int idx; float xo;
            if (c == 0) { idx = nn;       xo = x; }
            else        { idx = 399 - nn; xo = 512.0f - x; }
            out[((size_t)b * 400 + idx) * 2 + 0] = xo;
            out[((size_t)b * 400 + idx) * 2 + 1] = y;
        }
    }
}

extern "C" void kernel_launch(void* const* d_in, const int* in_sizes, int n_in,
                              void* d_out, int out_size) {
    const float4* in = (const float4*)d_in[0];
    float* out = (float*)d_out;

    kA_pass<<<4096, 256>>>(in);

    // k3a with PDL: launch overlaps kA's tail; device-side
    // cudaGridDependencySynchronize() enforces the data dependency.
    {
        cudaLaunchConfig_t cfg = {};
        cfg.gridDim  = dim3(128);
        cfg.blockDim = dim3(512);
        cudaLaunchAttribute attr[1];
        attr[0].id = cudaLaunchAttributeProgrammaticStreamSerialization;
        attr[0].val.programmaticStreamSerializationAllowed = 1;
        cfg.attrs = attr;
        cfg.numAttrs = 1;
        cudaLaunchKernelEx(&cfg, k3a_prelude, in);
    }
    // k3b with PDL on k3a.
    {
        cudaLaunchConfig_t cfg = {};
        cfg.gridDim  = dim3(512);
        cfg.blockDim = dim3(256);
        cudaLaunchAttribute attr[1];
        attr[0].id = cudaLaunchAttributeProgrammaticStreamSerialization;
        attr[0].val.programmaticStreamSerializationAllowed = 1;
        cfg.attrs = attr;
        cfg.numAttrs = 1;
        cudaLaunchKernelEx(&cfg, k3b_gauss, out);
    }
}